// round 9
// baseline (speedup 1.0000x reference)
#include <cuda_runtime.h>
#include <cuda_bf16.h>
#include <math.h>
#include <stdint.h>

#define CDIM 128
#define KDIM 128
#define MT 128
#define XS 72              // Psm row stride (bf16)
#define GRID 296

__device__ double g_acc;
__device__ unsigned int g_done;
__device__ float  g_qv[KDIM];
__device__ unsigned char g_pb[2 * KDIM * 64 * 2];  // protos bf16 [chunk][j][64]

__device__ __forceinline__ uint32_t smem_u32(const void* p) {
    uint32_t a;
    asm("{ .reg .u64 t; cvta.to.shared.u64 t, %1; cvt.u32.u64 %0, t; }" : "=r"(a) : "l"(p));
    return a;
}
__device__ __forceinline__ void ldsm4(uint32_t& r0, uint32_t& r1, uint32_t& r2,
                                      uint32_t& r3, uint32_t addr) {
    asm volatile("ldmatrix.sync.aligned.m8n8.x4.shared.b16 {%0,%1,%2,%3}, [%4];"
                 : "=r"(r0), "=r"(r1), "=r"(r2), "=r"(r3) : "r"(addr));
}

__global__ void k_prep(const float* __restrict__ protos)
{
    int t = threadIdx.x;
    if (blockIdx.x == 0) {
        if (t == 0) { g_acc = 0.0; g_done = 0u; }
        if (t < KDIM) {
            const float* pr = protos + t * CDIM;
            float s = 0.f;
            #pragma unroll 8
            for (int c = 0; c < CDIM; c++) { float v = pr[c]; s = fmaf(v, v, s); }
            g_qv[t] = 0.5f * s;
        }
    }
    int gt = blockIdx.x * blockDim.x + t;
    int stride = gridDim.x * blockDim.x;
    for (int idx = gt; idx < 2 * KDIM * 64; idx += stride) {
        int ch = idx >> 13, j = (idx >> 6) & 127, kk = idx & 63;
        ((__nv_bfloat16*)g_pb)[ch * KDIM * 64 + j * 64 + kk] =
            __float2bfloat16(protos[j * CDIM + ch * 64 + kk]);
    }
}

__device__ __forceinline__ void mma16816(float* c4, uint32_t a0, uint32_t a1,
                                         uint32_t a2, uint32_t a3,
                                         uint32_t b0, uint32_t b1) {
    asm volatile("mma.sync.aligned.m16n8k16.row.col.f32.bf16.bf16.f32 "
                 "{%0,%1,%2,%3}, {%4,%5,%6,%7}, {%8,%9}, {%0,%1,%2,%3};"
                 : "+f"(c4[0]), "+f"(c4[1]), "+f"(c4[2]), "+f"(c4[3])
                 : "r"(a0), "r"(a1), "r"(a2), "r"(a3), "r"(b0), "r"(b1));
}
__device__ __forceinline__ uint32_t pkbf(float a, float b) {
    __nv_bfloat162 h = __floats2bfloat162_rn(a, b);
    return *(uint32_t*)&h;
}

// Persistent pass: X loaded DIRECTLY global->registers (each element consumed
// by exactly one thread; LDG.64 fully coalesced at sector granularity).
// P resident in smem via ldmatrix. No mainloop barriers; 2 barriers/tile total.
__global__ void __launch_bounds__(256, 2)
k_main(const float* __restrict__ x, const int* __restrict__ labels,
       const int* __restrict__ kp, int N, float* __restrict__ out)
{
    __shared__ __nv_bfloat16 Psm[2 * KDIM * XS];   // 36864B
    __shared__ float  qs[KDIM];
    __shared__ float  rowsum[MT];
    __shared__ int    jbs[MT];
    __shared__ double wpart[8];

    int nt = (N + MT - 1) / MT;
    int t = threadIdx.x, wid = t >> 5, lane = t & 31;
    int g = lane >> 2, q = lane & 3;
    int rbase = wid * 16;
    int k = kp ? *kp : 128;

    // prime P (once) + qs
    if (t < 128) qs[t] = g_qv[t];
    #pragma unroll
    for (int it = 0; it < 8; it++) {               // 2048 x 16B
        int idx = t + it * 256;
        int ch = idx >> 10, rem = idx & 1023;
        int j = rem >> 3, seg = rem & 7;
        *(uint4*)((char*)Psm + (ch * 128 + j) * (XS * 2) + seg * 16) =
            *(const uint4*)(g_pb + ch * 16384 + j * 128 + seg * 16);
    }
    __syncthreads();

    // per-lane ldmatrix base (ch=0, kk=0): gsel selects {b0(j0),b1(j0),b0(j0+1),b1(j0+1)}
    uint32_t lm_base;
    {
        int gsel = lane >> 3, r = lane & 7;
        int row = (gsel >> 1) * 8 + r;
        lm_base = smem_u32(Psm) + (uint32_t)(row * XS + (gsel & 1) * 8) * 2u;
    }

    double nll_acc = 0.0;

    for (int tile = blockIdx.x; tile < nt; tile += GRID) {
        int tile0 = tile * MT;
        float acc[16][4];
        #pragma unroll
        for (int j = 0; j < 16; j++)
            #pragma unroll
            for (int n = 0; n < 4; n++) acc[j][n] = 0.f;
        float rs0 = 0.f, rs1 = 0.f;
        int myLab = 0;
        if (t < MT) myLab = labels[tile0 + t];

        int row0 = tile0 + rbase + g;  if (row0 > N - 9) row0 = N - 9; // safety (N mult of 128 anyway)
        const float* xr = x + (size_t)row0 * CDIM + q * 2;

        #pragma unroll
        for (int ch = 0; ch < 2; ch++) {
            // 16 independent LDG.64 -> high MLP, fully coalesced sectors
            float2 r0[8], r1[8];
            #pragma unroll
            for (int i = 0; i < 8; i++) {
                r0[i] = *(const float2*)(xr + ch * 64 + i * 8);
                r1[i] = *(const float2*)(xr + ch * 64 + i * 8 + 8 * CDIM);
            }
            uint32_t lmc = lm_base + (uint32_t)(ch * 128 * XS * 2);
            #pragma unroll
            for (int kk = 0; kk < 4; kk++) {
                float2 v00 = r0[2 * kk], v01 = r0[2 * kk + 1];
                float2 v10 = r1[2 * kk], v11 = r1[2 * kk + 1];
                rs0 += (__expf(v00.x) + __expf(v00.y)) + (__expf(v01.x) + __expf(v01.y));
                rs1 += (__expf(v10.x) + __expf(v10.y)) + (__expf(v11.x) + __expf(v11.y));
                uint32_t a0 = pkbf(v00.x, v00.y), a2 = pkbf(v01.x, v01.y);
                uint32_t a1 = pkbf(v10.x, v10.y), a3 = pkbf(v11.x, v11.y);
                uint32_t lmk = lmc + (uint32_t)(kk * 32);
                #pragma unroll
                for (int i = 0; i < 8; i++) {
                    uint32_t b0a, b1a, b0b, b1b;
                    ldsm4(b0a, b1a, b0b, b1b, lmk + (uint32_t)(i * 16 * XS * 2));
                    mma16816(acc[2 * i],     a0, a1, a2, a3, b0a, b1a);
                    mma16816(acc[2 * i + 1], a0, a1, a2, a3, b0b, b1b);
                }
            }
        }

        // rowsums (width-4 shfl)
        #pragma unroll
        for (int o = 1; o < 4; o <<= 1) {
            rs0 += __shfl_xor_sync(0xffffffffu, rs0, o, 4);
            rs1 += __shfl_xor_sync(0xffffffffu, rs1, o, 4);
        }
        if (q == 0) { rowsum[rbase + g] = rs0; rowsum[rbase + g + 8] = rs1; }

        // argmax -> effective label -> nll
        float bv0 = -3.0e38f, bv1 = -3.0e38f;
        int bj0 = 0, bj1 = 0;
        #pragma unroll
        for (int j0 = 0; j0 < 16; j0++) {
            int c0 = j0 * 8 + q * 2;
            float q0 = qs[c0], q1 = qs[c0 + 1];
            float s;
            s = acc[j0][0] - q0; if (s > bv0) { bv0 = s; bj0 = c0; }
            s = acc[j0][1] - q1; if (s > bv0) { bv0 = s; bj0 = c0 + 1; }
            s = acc[j0][2] - q0; if (s > bv1) { bv1 = s; bj1 = c0; }
            s = acc[j0][3] - q1; if (s > bv1) { bv1 = s; bj1 = c0 + 1; }
        }
        #pragma unroll
        for (int o = 1; o < 4; o <<= 1) {
            float v2 = __shfl_xor_sync(0xffffffffu, bv0, o, 4);
            int   j2 = __shfl_xor_sync(0xffffffffu, bj0, o, 4);
            if (v2 > bv0 || (v2 == bv0 && j2 < bj0)) { bv0 = v2; bj0 = j2; }
            v2 = __shfl_xor_sync(0xffffffffu, bv1, o, 4);
            j2 = __shfl_xor_sync(0xffffffffu, bj1, o, 4);
            if (v2 > bv1 || (v2 == bv1 && j2 < bj1)) { bv1 = v2; bj1 = j2; }
        }
        if (q == 0) { jbs[rbase + g] = bj0; jbs[rbase + g + 8] = bj1; }
        __syncthreads();

        if (t < MT && tile0 + t < N) {
            int leff = (myLab <= k - 1) ? myLab : jbs[t];
            float xl = x[(size_t)(tile0 + t) * CDIM + leff];   // L2-hot
            nll_acc += (double)(__logf(rowsum[t]) - xl);
        }
        __syncthreads();   // protect jbs/rowsum from next tile's writers
    }

    // final block reduction + fused finalization
    #pragma unroll
    for (int o = 16; o; o >>= 1) nll_acc += __shfl_xor_sync(0xffffffffu, nll_acc, o);
    if (lane == 0) wpart[wid] = nll_acc;
    __syncthreads();
    if (t == 0) {
        double s = 0.0;
        #pragma unroll
        for (int i = 0; i < 8; i++) s += wpart[i];
        atomicAdd(&g_acc, s);
        __threadfence();
        unsigned int done = atomicAdd(&g_done, 1u);
        if (done == gridDim.x - 1) out[0] = (float)(g_acc / (double)N);
    }
}

extern "C" void kernel_launch(void* const* d_in, const int* in_sizes, int n_in,
                              void* d_out, int out_size)
{
    const float* x      = (const float*)d_in[0];
    const int*   labels = (const int*)d_in[1];
    const float* protos = (const float*)d_in[2];
    const int*   kp     = (n_in > 3) ? (const int*)d_in[3] : nullptr;
    int N = in_sizes[0] / CDIM;

    k_prep<<<148, 256>>>(protos);
    k_main<<<GRID, 256>>>(x, labels, kp, N, (float*)d_out);
}

// round 11
// speedup vs baseline: 1.4680x; 1.4680x over previous
#include <cuda_runtime.h>
#include <cuda_bf16.h>
#include <math.h>
#include <stdint.h>

#define CDIM 128
#define KDIM 128
#define MT 128
#define GRID 296

__device__ double g_acc;
__device__ unsigned int g_done;
__device__ float  g_qv[KDIM];
__device__ unsigned char g_pb[2 * KDIM * 64 * 2];  // protos bf16 [chunk][j][64] tight

__device__ __forceinline__ uint32_t smem_u32(const void* p) {
    uint32_t a;
    asm("{ .reg .u64 t; cvta.to.shared.u64 t, %1; cvt.u32.u64 %0, t; }" : "=r"(a) : "l"(p));
    return a;
}
__device__ __forceinline__ void ldsm4(uint32_t& r0, uint32_t& r1, uint32_t& r2,
                                      uint32_t& r3, uint32_t addr) {
    asm volatile("ldmatrix.sync.aligned.m8n8.x4.shared.b16 {%0,%1,%2,%3}, [%4];"
                 : "=r"(r0), "=r"(r1), "=r"(r2), "=r"(r3) : "r"(addr));
}
__device__ __forceinline__ void mma16816(float* c4, uint32_t a0, uint32_t a1,
                                         uint32_t a2, uint32_t a3,
                                         uint32_t b0, uint32_t b1) {
    asm volatile("mma.sync.aligned.m16n8k16.row.col.f32.bf16.bf16.f32 "
                 "{%0,%1,%2,%3}, {%4,%5,%6,%7}, {%8,%9}, {%0,%1,%2,%3};"
                 : "+f"(c4[0]), "+f"(c4[1]), "+f"(c4[2]), "+f"(c4[3])
                 : "r"(a0), "r"(a1), "r"(a2), "r"(a3), "r"(b0), "r"(b1));
}
__device__ __forceinline__ uint32_t pkbf(float a, float b) {
    __nv_bfloat162 h = __floats2bfloat162_rn(a, b);
    return *(uint32_t*)&h;
}

__global__ void k_prep(const float* __restrict__ protos)
{
    int t = threadIdx.x;
    if (blockIdx.x == 0) {
        if (t == 0) { g_acc = 0.0; g_done = 0u; }
        if (t < KDIM) {
            const float* pr = protos + t * CDIM;
            float s = 0.f;
            #pragma unroll 8
            for (int c = 0; c < CDIM; c++) { float v = pr[c]; s = fmaf(v, v, s); }
            g_qv[t] = 0.5f * s;
        }
    }
    int gt = blockIdx.x * blockDim.x + t;
    int stride = gridDim.x * blockDim.x;
    for (int idx = gt; idx < 2 * KDIM * 64; idx += stride) {
        int ch = idx >> 13, j = (idx >> 6) & 127, kk = idx & 63;
        ((__nv_bfloat16*)g_pb)[ch * KDIM * 64 + j * 64 + kk] =
            __float2bfloat16(protos[j * CDIM + ch * 64 + kk]);
    }
}

// smem layout (dynamic):
//  [0,32768)        Psm bf16 [2ch][128 j][128B rows, 16B-swizzled]
//  [32768,98304)    Xb  bf16 [2 par][2ch][128 row][128B rows, swizzled]
//  then qs(512) rowsum[2](1024) redv[2](1024) redi[2](1024) wpart(64)
#define OFF_X   32768
#define OFF_QS  98304
#define OFF_RS  (OFF_QS + 512)
#define OFF_RV  (OFF_RS + 1024)
#define OFF_RI  (OFF_RV + 1024)
#define OFF_WP  (OFF_RI + 1024)
#define SMEMSZ  (OFF_WP + 64)

__global__ void __launch_bounds__(256, 2)
k_main(const float* __restrict__ x, const int* __restrict__ labels,
       const int* __restrict__ kp, int N, float* __restrict__ out)
{
    extern __shared__ char dsm[];
    char*  Pb = dsm;
    char*  Xc = dsm + OFF_X;
    float* qs = (float*)(dsm + OFF_QS);
    float* rowsum = (float*)(dsm + OFF_RS);    // [2][128]
    float* redv = (float*)(dsm + OFF_RV);      // [2][128]
    int*   redi = (int*)(dsm + OFF_RI);        // [2][128]
    double* wpart = (double*)(dsm + OFF_WP);

    int nt = (N + MT - 1) / MT;
    int t = threadIdx.x, wid = t >> 5, lane = t & 31;
    int g = lane >> 2, q = lane & 3;
    int mg = wid & 3, ng = wid >> 2;            // warp tile: rows mg*32+[0,32), cols ng*64+[0,64)
    int k = kp ? *kp : 128;

    uint32_t Pbase0 = smem_u32(Pb);
    uint32_t Xbase0 = smem_u32(Xc);

    // ---- prime P (swizzled) + qs
    if (t < 128) qs[t] = g_qv[t];
    #pragma unroll
    for (int it = 0; it < 8; it++) {            // 2048 x 16B chunks
        int idx = t + it * 256;
        int ch = idx >> 10, rem = idx & 1023;
        int j = rem >> 3, c16 = rem & 7;
        uint32_t off = (uint32_t)(ch * 16384 + j * 128 + ((c16 ^ (j & 7)) << 4));
        *(uint4*)(Pb + off) = *(const uint4*)(g_pb + ch * 16384 + j * 128 + c16 * 16);
    }

    // ldsm lane geometry (constant per lane)
    int rA = (lane & 7) + ((lane >> 3) & 1) * 8;        // A row-in-16
    int cA = lane >> 4;                                  // A k16-half
    int jB = ((lane >> 4) << 3) + (lane & 7);            // B row-in-16
    int cB = (lane >> 3) & 1;                            // B k16-half

    float pr[8];
    #pragma unroll
    for (int i = 0; i < 8; i++) pr[i] = 0.f;

    // stage tile `ti`, chunk `ch` into parity `par`; accumulates pr
    auto stage = [&](int ti, int ch, int par) {
        char* xb = Xc + par * 32768 + ch * 16384;
        #pragma unroll
        for (int i = 0; i < 8; i++) {
            int idx = t + i * 256;              // 0..2047 float4s
            int row = idx >> 4, seg = idx & 15;
            int grow = ti * MT + row; if (grow >= N) grow = N - 1;
            float4 v = *(const float4*)(x + (size_t)grow * CDIM + ch * 64 + seg * 4);
            pr[i] += (__expf(v.x) + __expf(v.y)) + (__expf(v.z) + __expf(v.w));
            uint2 pk; pk.x = pkbf(v.x, v.y); pk.y = pkbf(v.z, v.w);
            uint32_t off = (uint32_t)(row * 128 + (((seg >> 1) ^ (row & 7)) << 4) + (seg & 1) * 8);
            *(uint2*)(xb + off) = pk;
        }
    };

    // ---- prologue: stage tile=blockIdx into par 0
    {
        int ti = blockIdx.x;
        stage(ti, 0, 0);
        stage(ti, 1, 0);
        #pragma unroll
        for (int i = 0; i < 8; i++) {
            float s = pr[i];
            #pragma unroll
            for (int o = 8; o; o >>= 1) s += __shfl_xor_sync(0xffffffffu, s, o, 16);
            if ((t & 15) == 0) rowsum[(t >> 4) + i * 16] = s;   // rowsum[0][row]
            pr[i] = 0.f;
        }
    }

    double nll_acc = 0.0;
    int par = 0;

    for (int ti = blockIdx.x; ti < nt; ti += GRID) {
        __syncthreads();                         // Xb[par], rowsum[par] ready
        int tile0 = ti * MT;
        int myLab = 0;
        if (t < 128 && tile0 + t < N) myLab = labels[tile0 + t];

        float acc[2][8][4];
        #pragma unroll
        for (int m = 0; m < 2; m++)
            #pragma unroll
            for (int j = 0; j < 8; j++)
                #pragma unroll
                for (int n = 0; n < 4; n++) acc[m][j][n] = 0.f;

        int nti = ti + GRID;
        bool do_stage = (nti < nt);

        #pragma unroll
        for (int ch = 0; ch < 2; ch++) {
            uint32_t Xb = Xbase0 + (uint32_t)(par * 32768 + ch * 16384);
            uint32_t Pc = Pbase0 + (uint32_t)(ch * 16384);
            #pragma unroll
            for (int kk = 0; kk < 4; kk++) {
                uint32_t a[2][4];
                #pragma unroll
                for (int m = 0; m < 2; m++) {
                    int row = mg * 32 + m * 16 + rA;
                    uint32_t ad = Xb + (uint32_t)(row * 128 + (((kk * 2 + cA) ^ (rA & 7)) << 4));
                    ldsm4(a[m][0], a[m][1], a[m][2], a[m][3], ad);
                }
                #pragma unroll
                for (int i = 0; i < 4; i++) {
                    int j = ng * 64 + i * 16 + jB;
                    uint32_t bd = Pc + (uint32_t)(j * 128 + (((kk * 2 + cB) ^ (jB & 7)) << 4));
                    uint32_t b0a, b1a, b0b, b1b;
                    ldsm4(b0a, b1a, b0b, b1b, bd);
                    #pragma unroll
                    for (int m = 0; m < 2; m++) {
                        mma16816(acc[m][2 * i],     a[m][0], a[m][1], a[m][2], a[m][3], b0a, b1a);
                        mma16816(acc[m][2 * i + 1], a[m][0], a[m][1], a[m][2], a[m][3], b0b, b1b);
                    }
                }
            }
            if (do_stage) stage(nti, ch, par ^ 1);   // overlaps with MMA issue
        }
        if (do_stage) {
            #pragma unroll
            for (int i = 0; i < 8; i++) {
                float s = pr[i];
                #pragma unroll
                for (int o = 8; o; o >>= 1) s += __shfl_xor_sync(0xffffffffu, s, o, 16);
                if ((t & 15) == 0) rowsum[(par ^ 1) * 128 + (t >> 4) + i * 16] = s;
                pr[i] = 0.f;
            }
        }

        // ---- argmax within warp's m32 x n64 block
        float bv[4]; int bj[4];
        #pragma unroll
        for (int s4 = 0; s4 < 4; s4++) { bv[s4] = -3.0e38f; bj[s4] = 0; }
        #pragma unroll
        for (int m = 0; m < 2; m++)
            #pragma unroll
            for (int j = 0; j < 8; j++) {
                int c0 = ng * 64 + j * 8 + q * 2;
                float q0 = qs[c0], q1 = qs[c0 + 1];
                float s;
                s = acc[m][j][0] - q0; if (s > bv[m * 2])     { bv[m * 2] = s;     bj[m * 2] = c0; }
                s = acc[m][j][1] - q1; if (s > bv[m * 2])     { bv[m * 2] = s;     bj[m * 2] = c0 + 1; }
                s = acc[m][j][2] - q0; if (s > bv[m * 2 + 1]) { bv[m * 2 + 1] = s; bj[m * 2 + 1] = c0; }
                s = acc[m][j][3] - q1; if (s > bv[m * 2 + 1]) { bv[m * 2 + 1] = s; bj[m * 2 + 1] = c0 + 1; }
            }
        #pragma unroll
        for (int s4 = 0; s4 < 4; s4++) {
            #pragma unroll
            for (int o = 1; o < 4; o <<= 1) {
                float v2 = __shfl_xor_sync(0xffffffffu, bv[s4], o, 4);
                int   j2 = __shfl_xor_sync(0xffffffffu, bj[s4], o, 4);
                if (v2 > bv[s4] || (v2 == bv[s4] && j2 < bj[s4])) { bv[s4] = v2; bj[s4] = j2; }
            }
        }
        if (q == 0) {
            #pragma unroll
            for (int s4 = 0; s4 < 4; s4++) {
                int row = mg * 32 + (s4 >> 1) * 16 + (s4 & 1) * 8 + g;
                redv[ng * 128 + row] = bv[s4];
                redi[ng * 128 + row] = bj[s4];
            }
        }
        __syncthreads();

        if (t < 128 && tile0 + t < N) {
            float v0 = redv[t], v1 = redv[128 + t];
            int jb = (v1 > v0) ? redi[128 + t] : redi[t];   // tie -> lower j (group 0)
            int leff = (myLab <= k - 1) ? myLab : jb;
            float xl = x[(size_t)(tile0 + t) * CDIM + leff];    // L2-resident
            nll_acc += (double)(__logf(rowsum[par * 128 + t]) - xl);
        }
        par ^= 1;
    }

    // ---- final reduction + fused finalization
    #pragma unroll
    for (int o = 16; o; o >>= 1) nll_acc += __shfl_xor_sync(0xffffffffu, nll_acc, o);
    if (lane == 0) wpart[wid] = nll_acc;
    __syncthreads();
    if (t == 0) {
        double s = 0.0;
        #pragma unroll
        for (int i = 0; i < 8; i++) s += wpart[i];
        atomicAdd(&g_acc, s);
        __threadfence();
        unsigned int done = atomicAdd(&g_done, 1u);
        if (done == gridDim.x - 1) out[0] = (float)(g_acc / (double)N);
    }
}

extern "C" void kernel_launch(void* const* d_in, const int* in_sizes, int n_in,
                              void* d_out, int out_size)
{
    const float* x      = (const float*)d_in[0];
    const int*   labels = (const int*)d_in[1];
    const float* protos = (const float*)d_in[2];
    const int*   kp     = (n_in > 3) ? (const int*)d_in[3] : nullptr;
    int N = in_sizes[0] / CDIM;

    cudaFuncSetAttribute(k_main, cudaFuncAttributeMaxDynamicSharedMemorySize, SMEMSZ);
    k_prep<<<148, 256>>>(protos);
    k_main<<<GRID, 256, SMEMSZ>>>(x, labels, kp, N, (float*)d_out);
}

// round 12
// speedup vs baseline: 1.5014x; 1.0228x over previous
#include <cuda_runtime.h>
#include <cuda_bf16.h>
#include <math.h>
#include <stdint.h>

#define CDIM 128
#define KDIM 128
#define MT 64
#define GRID 444

__device__ double g_acc;
__device__ unsigned int g_done;
__device__ float  g_qv[KDIM];
__device__ unsigned char g_pb[2 * KDIM * 64 * 2];  // protos bf16 [chunk][j][64] tight

__device__ __forceinline__ uint32_t smem_u32(const void* p) {
    uint32_t a;
    asm("{ .reg .u64 t; cvta.to.shared.u64 t, %1; cvt.u32.u64 %0, t; }" : "=r"(a) : "l"(p));
    return a;
}
__device__ __forceinline__ void ldsm4(uint32_t& r0, uint32_t& r1, uint32_t& r2,
                                      uint32_t& r3, uint32_t addr) {
    asm volatile("ldmatrix.sync.aligned.m8n8.x4.shared.b16 {%0,%1,%2,%3}, [%4];"
                 : "=r"(r0), "=r"(r1), "=r"(r2), "=r"(r3) : "r"(addr));
}
__device__ __forceinline__ void mma16816(float* c4, uint32_t a0, uint32_t a1,
                                         uint32_t a2, uint32_t a3,
                                         uint32_t b0, uint32_t b1) {
    asm volatile("mma.sync.aligned.m16n8k16.row.col.f32.bf16.bf16.f32 "
                 "{%0,%1,%2,%3}, {%4,%5,%6,%7}, {%8,%9}, {%0,%1,%2,%3};"
                 : "+f"(c4[0]), "+f"(c4[1]), "+f"(c4[2]), "+f"(c4[3])
                 : "r"(a0), "r"(a1), "r"(a2), "r"(a3), "r"(b0), "r"(b1));
}
__device__ __forceinline__ uint32_t pkbf(float a, float b) {
    __nv_bfloat162 h = __floats2bfloat162_rn(a, b);
    return *(uint32_t*)&h;
}

__global__ void k_prep(const float* __restrict__ protos)
{
    int t = threadIdx.x;
    if (blockIdx.x == 0) {
        if (t == 0) { g_acc = 0.0; g_done = 0u; }
        if (t < KDIM) {
            const float* pr = protos + t * CDIM;
            float s = 0.f;
            #pragma unroll 8
            for (int c = 0; c < CDIM; c++) { float v = pr[c]; s = fmaf(v, v, s); }
            g_qv[t] = 0.5f * s;
        }
    }
    int gt = blockIdx.x * blockDim.x + t;
    int stride = gridDim.x * blockDim.x;
    for (int idx = gt; idx < 2 * KDIM * 64; idx += stride) {
        int ch = idx >> 13, j = (idx >> 6) & 127, kk = idx & 63;
        ((__nv_bfloat16*)g_pb)[ch * KDIM * 64 + j * 64 + kk] =
            __float2bfloat16(protos[j * CDIM + ch * 64 + kk]);
    }
}

// smem (dynamic) per CTA:
//  [0,32768)       P bf16 [2ch][128 j][128B rows, 16B-swizzled]
//  [32768,65536)   X bf16 [2 par][2 ch][64 row][128B rows, swizzled]
//  then qs(512) rowsum[2][64](512) redv[2][64](512) redi[2][64](512) wpart(64)
#define OFF_X   32768
#define OFF_QS  65536
#define OFF_RS  (OFF_QS + 512)
#define OFF_RV  (OFF_RS + 512)
#define OFF_RI  (OFF_RV + 512)
#define OFF_WP  (OFF_RI + 512)
#define SMEMSZ  (OFF_WP + 64)

__global__ void __launch_bounds__(256, 3)
k_main(const float* __restrict__ x, const int* __restrict__ labels,
       const int* __restrict__ kp, int N, float* __restrict__ out)
{
    extern __shared__ char dsm[];
    char*  Pb = dsm;
    char*  Xc = dsm + OFF_X;
    float* qs = (float*)(dsm + OFF_QS);
    float* rowsum = (float*)(dsm + OFF_RS);    // [2 par][64]
    float* redv = (float*)(dsm + OFF_RV);      // [2 ng][64]
    int*   redi = (int*)(dsm + OFF_RI);        // [2 ng][64]
    double* wpart = (double*)(dsm + OFF_WP);

    int nt = (N + MT - 1) / MT;
    int t = threadIdx.x, wid = t >> 5, lane = t & 31;
    int g = lane >> 2, q = lane & 3;
    int mg = wid & 3, ng = wid >> 2;            // warp tile: rows mg*16+[0,16), cols ng*64+[0,64)
    int k = kp ? *kp : 128;

    uint32_t Pbase0 = smem_u32(Pb);
    uint32_t Xbase0 = smem_u32(Xc);

    // ---- prime P (swizzled) + qs
    if (t < 128) qs[t] = g_qv[t];
    #pragma unroll
    for (int it = 0; it < 8; it++) {            // 2048 x 16B
        int idx = t + it * 256;
        int ch = idx >> 10, rem = idx & 1023;
        int j = rem >> 3, c16 = rem & 7;
        uint32_t off = (uint32_t)(ch * 16384 + j * 128 + ((c16 ^ (j & 7)) << 4));
        *(uint4*)(Pb + off) = *(const uint4*)(g_pb + ch * 16384 + j * 128 + c16 * 16);
    }

    // ldsm lane geometry
    int rA = (lane & 7) + ((lane >> 3) & 1) * 8;        // A row-in-16
    int cA = lane >> 4;                                  // A k16-half
    int jB = ((lane >> 4) << 3) + (lane & 7);            // B row-in-16
    int cB = (lane >> 3) & 1;                            // B k16-half

    float pr[4];
    #pragma unroll
    for (int i = 0; i < 4; i++) pr[i] = 0.f;

    // stage tile `ti`, chunk `ch` into parity `par`; accumulates pr
    auto stage = [&](int ti, int ch, int par) {
        char* xb = Xc + par * 16384 + ch * 8192;
        #pragma unroll
        for (int i = 0; i < 4; i++) {
            int idx = t + i * 256;              // 0..1023 float4s
            int row = idx >> 4, seg = idx & 15;
            int grow = ti * MT + row; if (grow >= N) grow = N - 1;
            float4 v = *(const float4*)(x + (size_t)grow * CDIM + ch * 64 + seg * 4);
            pr[i] += (__expf(v.x) + __expf(v.y)) + (__expf(v.z) + __expf(v.w));
            uint2 pk; pk.x = pkbf(v.x, v.y); pk.y = pkbf(v.z, v.w);
            uint32_t off = (uint32_t)(row * 128 + (((seg >> 1) ^ (row & 7)) << 4) + (seg & 1) * 8);
            *(uint2*)(xb + off) = pk;
        }
    };

    // ---- prologue: stage tile=blockIdx into par 0
    {
        int ti = blockIdx.x;
        if (ti < nt) { stage(ti, 0, 0); stage(ti, 1, 0); }
        #pragma unroll
        for (int i = 0; i < 4; i++) {
            float s = pr[i];
            #pragma unroll
            for (int o = 8; o; o >>= 1) s += __shfl_xor_sync(0xffffffffu, s, o, 16);
            if ((t & 15) == 0) rowsum[(t >> 4) + i * 16] = s;   // rowsum[0][row]
            pr[i] = 0.f;
        }
    }

    double nll_acc = 0.0;
    int par = 0;

    for (int ti = blockIdx.x; ti < nt; ti += GRID) {
        __syncthreads();                         // X[par], rowsum[par] ready
        int tile0 = ti * MT;
        int myLab = 0;
        if (t < MT && tile0 + t < N) myLab = labels[tile0 + t];

        float acc[8][4];
        #pragma unroll
        for (int j = 0; j < 8; j++)
            #pragma unroll
            for (int n = 0; n < 4; n++) acc[j][n] = 0.f;

        int nti = ti + GRID;
        bool do_stage = (nti < nt);

        #pragma unroll
        for (int ch = 0; ch < 2; ch++) {
            uint32_t Xb = Xbase0 + (uint32_t)(par * 16384 + ch * 8192);
            uint32_t Pc = Pbase0 + (uint32_t)(ch * 16384);
            #pragma unroll
            for (int kk = 0; kk < 4; kk++) {
                uint32_t a0, a1, a2, a3;
                {
                    int row = mg * 16 + rA;
                    uint32_t ad = Xb + (uint32_t)(row * 128 + (((kk * 2 + cA) ^ (rA & 7)) << 4));
                    ldsm4(a0, a1, a2, a3, ad);
                }
                #pragma unroll
                for (int i = 0; i < 4; i++) {
                    int j = ng * 64 + i * 16 + jB;
                    uint32_t bd = Pc + (uint32_t)(j * 128 + (((kk * 2 + cB) ^ (jB & 7)) << 4));
                    uint32_t b0a, b1a, b0b, b1b;
                    ldsm4(b0a, b1a, b0b, b1b, bd);
                    mma16816(acc[2 * i],     a0, a1, a2, a3, b0a, b1a);
                    mma16816(acc[2 * i + 1], a0, a1, a2, a3, b0b, b1b);
                }
            }
            if (do_stage) stage(nti, ch, par ^ 1);   // overlaps with MMA issue
        }
        if (do_stage) {
            #pragma unroll
            for (int i = 0; i < 4; i++) {
                float s = pr[i];
                #pragma unroll
                for (int o = 8; o; o >>= 1) s += __shfl_xor_sync(0xffffffffu, s, o, 16);
                if ((t & 15) == 0) rowsum[(par ^ 1) * 64 + (t >> 4) + i * 16] = s;
                pr[i] = 0.f;
            }
        }

        // ---- argmax within warp's m16 x n64 block
        float bv0 = -3.0e38f, bv1 = -3.0e38f;
        int bj0 = 0, bj1 = 0;
        #pragma unroll
        for (int j = 0; j < 8; j++) {
            int c0 = ng * 64 + j * 8 + q * 2;
            float q0 = qs[c0], q1 = qs[c0 + 1];
            float s;
            s = acc[j][0] - q0; if (s > bv0) { bv0 = s; bj0 = c0; }
            s = acc[j][1] - q1; if (s > bv0) { bv0 = s; bj0 = c0 + 1; }
            s = acc[j][2] - q0; if (s > bv1) { bv1 = s; bj1 = c0; }
            s = acc[j][3] - q1; if (s > bv1) { bv1 = s; bj1 = c0 + 1; }
        }
        #pragma unroll
        for (int o = 1; o < 4; o <<= 1) {
            float v2 = __shfl_xor_sync(0xffffffffu, bv0, o, 4);
            int   j2 = __shfl_xor_sync(0xffffffffu, bj0, o, 4);
            if (v2 > bv0 || (v2 == bv0 && j2 < bj0)) { bv0 = v2; bj0 = j2; }
            v2 = __shfl_xor_sync(0xffffffffu, bv1, o, 4);
            j2 = __shfl_xor_sync(0xffffffffu, bj1, o, 4);
            if (v2 > bv1 || (v2 == bv1 && j2 < bj1)) { bv1 = v2; bj1 = j2; }
        }
        if (q == 0) {
            int row = mg * 16 + g;
            redv[ng * 64 + row] = bv0; redi[ng * 64 + row] = bj0;
            redv[ng * 64 + row + 8] = bv1; redi[ng * 64 + row + 8] = bj1;
        }
        __syncthreads();

        if (t < MT && tile0 + t < N) {
            float v0 = redv[t], v1 = redv[64 + t];
            int jb = (v1 > v0) ? redi[64 + t] : redi[t];   // tie -> lower j (group 0)
            int leff = (myLab <= k - 1) ? myLab : jb;
            float xl = x[(size_t)(tile0 + t) * CDIM + leff];    // L2-resident
            nll_acc += (double)(__logf(rowsum[par * 64 + t]) - xl);
        }
        par ^= 1;
    }

    // ---- final reduction + fused finalization
    #pragma unroll
    for (int o = 16; o; o >>= 1) nll_acc += __shfl_xor_sync(0xffffffffu, nll_acc, o);
    if (lane == 0) wpart[wid] = nll_acc;
    __syncthreads();
    if (t == 0) {
        double s = 0.0;
        #pragma unroll
        for (int i = 0; i < 8; i++) s += wpart[i];
        atomicAdd(&g_acc, s);
        __threadfence();
        unsigned int done = atomicAdd(&g_done, 1u);
        if (done == gridDim.x - 1) out[0] = (float)(g_acc / (double)N);
    }
}

extern "C" void kernel_launch(void* const* d_in, const int* in_sizes, int n_in,
                              void* d_out, int out_size)
{
    const float* x      = (const float*)d_in[0];
    const int*   labels = (const int*)d_in[1];
    const float* protos = (const float*)d_in[2];
    const int*   kp     = (n_in > 3) ? (const int*)d_in[3] : nullptr;
    int N = in_sizes[0] / CDIM;

    cudaFuncSetAttribute(k_main, cudaFuncAttributeMaxDynamicSharedMemorySize, SMEMSZ);
    k_prep<<<148, 256>>>(protos);
    k_main<<<GRID, 256, SMEMSZ>>>(x, labels, kp, N, (float*)d_out);
}

// round 13
// speedup vs baseline: 1.6127x; 1.0741x over previous
#include <cuda_runtime.h>
#include <cuda_bf16.h>
#include <math.h>
#include <stdint.h>

#define CDIM 128
#define KDIM 128
#define MT 64
#define GRID 444

__device__ double g_part[GRID];
__device__ unsigned int g_done;          // monotone ticket (never reset; % GRID)

__device__ __forceinline__ uint32_t smem_u32(const void* p) {
    uint32_t a;
    asm("{ .reg .u64 t; cvta.to.shared.u64 t, %1; cvt.u32.u64 %0, t; }" : "=r"(a) : "l"(p));
    return a;
}
__device__ __forceinline__ void ldsm4(uint32_t& r0, uint32_t& r1, uint32_t& r2,
                                      uint32_t& r3, uint32_t addr) {
    asm volatile("ldmatrix.sync.aligned.m8n8.x4.shared.b16 {%0,%1,%2,%3}, [%4];"
                 : "=r"(r0), "=r"(r1), "=r"(r2), "=r"(r3) : "r"(addr));
}
__device__ __forceinline__ void mma16816(float* c4, uint32_t a0, uint32_t a1,
                                         uint32_t a2, uint32_t a3,
                                         uint32_t b0, uint32_t b1) {
    asm volatile("mma.sync.aligned.m16n8k16.row.col.f32.bf16.bf16.f32 "
                 "{%0,%1,%2,%3}, {%4,%5,%6,%7}, {%8,%9}, {%0,%1,%2,%3};"
                 : "+f"(c4[0]), "+f"(c4[1]), "+f"(c4[2]), "+f"(c4[3])
                 : "r"(a0), "r"(a1), "r"(a2), "r"(a3), "r"(b0), "r"(b1));
}
__device__ __forceinline__ uint32_t pkbf(float a, float b) {
    __nv_bfloat162 h = __floats2bfloat162_rn(a, b);
    return *(uint32_t*)&h;
}

// smem layout:
//  [0,32768)      P  bf16 [2ch][128 j][128B rows, 16B-swizzled]
//  [32768,65536)  X  bf16 [2 par][2 ch][64 row][128B rows, swizzled]
//  qs(512) rowsum[3][64](768) redv[2][2][64](1024) redi(1024) wpart(64) flag(16)
#define OFF_X   32768
#define OFF_QS  65536
#define OFF_RS  (OFF_QS + 512)
#define OFF_RV  (OFF_RS + 768)
#define OFF_RI  (OFF_RV + 1024)
#define OFF_WP  (OFF_RI + 1024)
#define OFF_FL  (OFF_WP + 64)
#define SMEMSZ  (OFF_FL + 16)

__global__ void __launch_bounds__(256, 3)
k_main(const float* __restrict__ x, const int* __restrict__ labels,
       const float* __restrict__ protos, const int* __restrict__ kp,
       int N, float* __restrict__ out)
{
    extern __shared__ char dsm[];
    char*  Pb = dsm;
    char*  Xc = dsm + OFF_X;
    float* qs = (float*)(dsm + OFF_QS);
    float* rowsum = (float*)(dsm + OFF_RS);    // [3][64]
    float* redv = (float*)(dsm + OFF_RV);      // [2 par][2 ng][64]
    int*   redi = (int*)(dsm + OFF_RI);
    double* wpart = (double*)(dsm + OFF_WP);
    int*   flag = (int*)(dsm + OFF_FL);

    int nt = (N + MT - 1) / MT;
    int t = threadIdx.x, wid = t >> 5, lane = t & 31;
    int g = lane >> 2, q = lane & 3;
    int mg = wid & 3, ng = wid >> 2;           // warp tile: rows mg*16+[0,16), cols ng*64+[0,64)
    int k = kp ? *kp : 128;

    uint32_t Pbase0 = smem_u32(Pb);
    uint32_t Xbase0 = smem_u32(Xc);

    // ---- prime P (bf16, swizzled) + qs directly from protos (L2-hot)
    #pragma unroll
    for (int i = 0; i < 16; i++) {             // 4096 x 8B units
        int idx = t + i * 256;
        int ch = idx >> 11, rem = idx & 2047;
        int j = rem >> 4, u8 = rem & 15;
        float4 v = *(const float4*)(protos + j * CDIM + ch * 64 + u8 * 4);
        uint2 pk; pk.x = pkbf(v.x, v.y); pk.y = pkbf(v.z, v.w);
        uint32_t off = (uint32_t)(ch * 16384 + j * 128 +
                                  (((u8 >> 1) ^ (j & 7)) << 4) + (u8 & 1) * 8);
        *(uint2*)(Pb + off) = pk;
    }
    if (t < 128) {
        const float4* pr4 = (const float4*)(protos + t * CDIM);
        float s = 0.f;
        #pragma unroll 8
        for (int c = 0; c < 32; c++) {
            float4 v = pr4[c];
            s = fmaf(v.x, v.x, fmaf(v.y, v.y, fmaf(v.z, v.z, fmaf(v.w, v.w, s))));
        }
        qs[t] = 0.5f * s;
    }

    // ldsm lane geometry
    int rA = (lane & 7) + ((lane >> 3) & 1) * 8;
    int cA = lane >> 4;
    int jB = ((lane >> 4) << 3) + (lane & 7);
    int cB = (lane >> 3) & 1;

    float pr[4];
    #pragma unroll
    for (int i = 0; i < 4; i++) pr[i] = 0.f;

    auto stage = [&](int ti, int ch, int buf) {
        char* xb = Xc + buf * 16384 + ch * 8192;
        #pragma unroll
        for (int i = 0; i < 4; i++) {
            int idx = t + i * 256;
            int row = idx >> 4, seg = idx & 15;
            int grow = ti * MT + row; if (grow >= N) grow = N - 1;
            float4 v = *(const float4*)(x + (size_t)grow * CDIM + ch * 64 + seg * 4);
            pr[i] += (__expf(v.x) + __expf(v.y)) + (__expf(v.z) + __expf(v.w));
            uint2 pk; pk.x = pkbf(v.x, v.y); pk.y = pkbf(v.z, v.w);
            uint32_t off = (uint32_t)(row * 128 + (((seg >> 1) ^ (row & 7)) << 4) + (seg & 1) * 8);
            *(uint2*)(xb + off) = pk;
        }
    };

    // ---- prologue: stage T0 into buf0, rowsum[0]; prefetch labels(T0)
    int labCur = 0, labPrev = 0;
    {
        int ti0 = blockIdx.x;
        if (t < MT && ti0 < nt) labCur = labels[ti0 * MT + t];
        if (ti0 < nt) { stage(ti0, 0, 0); stage(ti0, 1, 0); }
        #pragma unroll
        for (int i = 0; i < 4; i++) {
            float s = pr[i];
            #pragma unroll
            for (int o = 8; o; o >>= 1) s += __shfl_xor_sync(0xffffffffu, s, o, 16);
            if ((t & 15) == 0) rowsum[(t >> 4) + i * 16] = s;
            pr[i] = 0.f;
        }
    }

    double nll_acc = 0.0;
    int it = 0;

    for (int ti = blockIdx.x; ti < nt; ti += GRID, it++) {
        int par = it & 1;
        __syncthreads();                       // X[par], rowsum(T_it), redv(T_{it-1}) ready

        // ---- CE for previous tile (covers this iter's LDG latency window too)
        if (it > 0 && t < MT) {
            int prow = (ti - GRID) * MT + t;
            float v0 = redv[(par ^ 1) * 128 + t], v1 = redv[(par ^ 1) * 128 + 64 + t];
            int jb = (v1 > v0) ? redi[(par ^ 1) * 128 + 64 + t] : redi[(par ^ 1) * 128 + t];
            int leff = (labPrev <= k - 1) ? labPrev : jb;
            float xl = x[(size_t)prow * CDIM + leff];
            nll_acc += (double)(__logf(rowsum[((it - 1) % 3) * 64 + t]) - xl);
        }
        labPrev = labCur;

        float acc[8][4];
        #pragma unroll
        for (int j = 0; j < 8; j++)
            #pragma unroll
            for (int n = 0; n < 4; n++) acc[j][n] = 0.f;

        int nti = ti + GRID;
        bool ds = (nti < nt);

        #pragma unroll
        for (int ch = 0; ch < 2; ch++) {
            uint32_t Xb = Xbase0 + (uint32_t)(par * 16384 + ch * 8192);
            uint32_t Pc = Pbase0 + (uint32_t)(ch * 16384);
            #pragma unroll
            for (int kk = 0; kk < 4; kk++) {
                uint32_t a0, a1, a2, a3;
                {
                    int row = mg * 16 + rA;
                    uint32_t ad = Xb + (uint32_t)(row * 128 + (((kk * 2 + cA) ^ (rA & 7)) << 4));
                    ldsm4(a0, a1, a2, a3, ad);
                }
                #pragma unroll
                for (int i = 0; i < 4; i++) {
                    int j = ng * 64 + i * 16 + jB;
                    uint32_t bd = Pc + (uint32_t)(j * 128 + (((kk * 2 + cB) ^ (jB & 7)) << 4));
                    uint32_t b0a, b1a, b0b, b1b;
                    ldsm4(b0a, b1a, b0b, b1b, bd);
                    mma16816(acc[2 * i],     a0, a1, a2, a3, b0a, b1a);
                    mma16816(acc[2 * i + 1], a0, a1, a2, a3, b0b, b1b);
                }
            }
            if (ds) stage(nti, ch, par ^ 1);   // LDGs issue here; covered by argmax below
        }
        if (ds && t < MT) labCur = labels[nti * MT + t];

        // ---- argmax within warp's m16 x n64 block (fills LDG shadow)
        float bv0 = -3.0e38f, bv1 = -3.0e38f;
        int bj0 = 0, bj1 = 0;
        #pragma unroll
        for (int j = 0; j < 8; j++) {
            int c0 = ng * 64 + j * 8 + q * 2;
            float q0 = qs[c0], q1 = qs[c0 + 1];
            float s;
            s = acc[j][0] - q0; if (s > bv0) { bv0 = s; bj0 = c0; }
            s = acc[j][1] - q1; if (s > bv0) { bv0 = s; bj0 = c0 + 1; }
            s = acc[j][2] - q0; if (s > bv1) { bv1 = s; bj1 = c0; }
            s = acc[j][3] - q1; if (s > bv1) { bv1 = s; bj1 = c0 + 1; }
        }
        #pragma unroll
        for (int o = 1; o < 4; o <<= 1) {
            float v2 = __shfl_xor_sync(0xffffffffu, bv0, o, 4);
            int   j2 = __shfl_xor_sync(0xffffffffu, bj0, o, 4);
            if (v2 > bv0 || (v2 == bv0 && j2 < bj0)) { bv0 = v2; bj0 = j2; }
            v2 = __shfl_xor_sync(0xffffffffu, bv1, o, 4);
            j2 = __shfl_xor_sync(0xffffffffu, bj1, o, 4);
            if (v2 > bv1 || (v2 == bv1 && j2 < bj1)) { bv1 = v2; bj1 = j2; }
        }
        if (q == 0) {
            int row = mg * 16 + g;
            redv[par * 128 + ng * 64 + row] = bv0;     redi[par * 128 + ng * 64 + row] = bj0;
            redv[par * 128 + ng * 64 + row + 8] = bv1; redi[par * 128 + ng * 64 + row + 8] = bj1;
        }

        if (ds) {                              // rowsum for tile nti -> ring (it+1)%3
            #pragma unroll
            for (int i = 0; i < 4; i++) {
                float s = pr[i];
                #pragma unroll
                for (int o = 8; o; o >>= 1) s += __shfl_xor_sync(0xffffffffu, s, o, 16);
                if ((t & 15) == 0) rowsum[((it + 1) % 3) * 64 + (t >> 4) + i * 16] = s;
                pr[i] = 0.f;
            }
        }
    }

    // ---- trailing CE for the last tile
    __syncthreads();
    if (it > 0 && t < MT) {
        int itL = it - 1, parL = itL & 1;
        int prow = (blockIdx.x + itL * GRID) * MT + t;
        if (prow < N) {
            float v0 = redv[parL * 128 + t], v1 = redv[parL * 128 + 64 + t];
            int jb = (v1 > v0) ? redi[parL * 128 + 64 + t] : redi[parL * 128 + t];
            int leff = (labPrev <= k - 1) ? labPrev : jb;
            float xl = x[(size_t)prow * CDIM + leff];
            nll_acc += (double)(__logf(rowsum[(itL % 3) * 64 + t]) - xl);
        }
    }

    // ---- CTA partial + ticketed finalization (reset-free across graph replays)
    #pragma unroll
    for (int o = 16; o; o >>= 1) nll_acc += __shfl_xor_sync(0xffffffffu, nll_acc, o);
    if (lane == 0) wpart[wid] = nll_acc;
    __syncthreads();
    if (t == 0) {
        double s = 0.0;
        #pragma unroll
        for (int i = 0; i < 8; i++) s += wpart[i];
        g_part[blockIdx.x] = s;
        __threadfence();
        unsigned int tk = atomicAdd(&g_done, 1u);
        flag[0] = ((tk % (unsigned)gridDim.x) == (unsigned)gridDim.x - 1u) ? 1 : 0;
    }
    __syncthreads();
    if (flag[0]) {                             // last CTA: all threads sum partials
        double s = 0.0;
        for (int i = t; i < GRID; i += 256) s += g_part[i];
        #pragma unroll
        for (int o = 16; o; o >>= 1) s += __shfl_xor_sync(0xffffffffu, s, o);
        if (lane == 0) wpart[wid] = s;
        __syncthreads();
        if (t == 0) {
            double f = 0.0;
            #pragma unroll
            for (int i = 0; i < 8; i++) f += wpart[i];
            out[0] = (float)(f / (double)N);
        }
    }
}

extern "C" void kernel_launch(void* const* d_in, const int* in_sizes, int n_in,
                              void* d_out, int out_size)
{
    const float* x      = (const float*)d_in[0];
    const int*   labels = (const int*)d_in[1];
    const float* protos = (const float*)d_in[2];
    const int*   kp     = (n_in > 3) ? (const int*)d_in[3] : nullptr;
    int N = in_sizes[0] / CDIM;

    cudaFuncSetAttribute(k_main, cudaFuncAttributeMaxDynamicSharedMemorySize, SMEMSZ);
    k_main<<<GRID, 256, SMEMSZ>>>(x, labels, protos, kp, N, (float*)d_out);
}